// round 15
// baseline (speedup 1.0000x reference)
#include <cuda_runtime.h>
#include <cuda_fp16.h>
#include <cstdint>

typedef unsigned int uint;

// Problem constants
constexpr int B_  = 2;
constexpr int C_  = 256;
constexpr int N_  = 4096;
constexpr int H_  = 8;
constexpr int HD_ = 32;
constexpr int QKV3 = 3 * C_;                 // 768
constexpr float SCALE_ = 0.17677669529663689f; // 32^-0.5
constexpr float LOG2E_ = 1.4426950408889634f;

// Scratch (device globals). Q hi-only; K/V/att split fp16 hi/lo.
__device__ __half g_qh[(size_t)B_ * H_ * N_ * HD_];
__device__ __half g_kh[(size_t)B_ * H_ * N_ * HD_];
__device__ __half g_kl[(size_t)B_ * H_ * N_ * HD_];
__device__ __half g_vh[(size_t)B_ * H_ * N_ * HD_];
__device__ __half g_vl[(size_t)B_ * H_ * N_ * HD_];
__device__ __half g_ah[(size_t)B_ * N_ * C_];   // attention out hi, [B*N][C]
__device__ __half g_al[(size_t)B_ * N_ * C_];   // attention out lo

// ---- helpers ----------------------------------------------------------------
__device__ __forceinline__ uint32_t smem_u32(const void* p) {
    uint32_t a;
    asm("{ .reg .u64 t; cvta.to.shared.u64 t, %1; cvt.u32.u64 %0, t; }" : "=r"(a) : "l"(p));
    return a;
}
__device__ __forceinline__ void ldsm4(uint* r, uint32_t addr) {
    asm volatile("ldmatrix.sync.aligned.m8n8.x4.shared.b16 {%0,%1,%2,%3}, [%4];"
        : "=r"(r[0]), "=r"(r[1]), "=r"(r[2]), "=r"(r[3]) : "r"(addr));
}
__device__ __forceinline__ void ldsm4t(uint* r, uint32_t addr) {
    asm volatile("ldmatrix.sync.aligned.m8n8.x4.trans.shared.b16 {%0,%1,%2,%3}, [%4];"
        : "=r"(r[0]), "=r"(r[1]), "=r"(r[2]), "=r"(r[3]) : "r"(addr));
}
__device__ __forceinline__ void mma16816(float* d, const uint* a, uint b0, uint b1) {
    asm volatile(
        "mma.sync.aligned.m16n8k16.row.col.f32.f16.f16.f32 "
        "{%0,%1,%2,%3}, {%4,%5,%6,%7}, {%8,%9}, {%0,%1,%2,%3};"
        : "+f"(d[0]), "+f"(d[1]), "+f"(d[2]), "+f"(d[3])
        : "r"(a[0]), "r"(a[1]), "r"(a[2]), "r"(a[3]), "r"(b0), "r"(b1));
}
__device__ __forceinline__ uint pack_h2(__half a, __half b) {
    unsigned short x = *(unsigned short*)&a, y = *(unsigned short*)&b;
    uint r; asm("mov.b32 %0, {%1, %2};" : "=r"(r) : "h"(x), "h"(y)); return r;
}
__device__ __forceinline__ uint cvt_h2(float a, float b) {
    uint r; asm("cvt.rn.f16x2.f32 %0, %2, %1;" : "=r"(r) : "f"(a), "f"(b)); return r;
}
__device__ __forceinline__ uint ex2h2(uint x) {    // packed fp16x2 exp2
    uint r; asm("ex2.approx.f16x2 %0, %1;" : "=r"(r) : "r"(x)); return r;
}
__device__ __forceinline__ void cp16(uint32_t saddr, const void* gptr) {
    asm volatile("cp.async.cg.shared.global [%0], [%1], 16;" :: "r"(saddr), "l"(gptr));
}
#define CP_COMMIT() asm volatile("cp.async.commit_group;" ::: "memory")
#define CP_WAIT2()  asm volatile("cp.async.wait_group 2;" ::: "memory")

// split 4 floats to hi/lo packed pairs
__device__ __forceinline__ void split4(const float* v, uint2& hu, uint2& lu) {
    __half h0 = __float2half_rn(v[0]), h1 = __float2half_rn(v[1]);
    __half h2 = __float2half_rn(v[2]), h3 = __float2half_rn(v[3]);
    __half l0 = __float2half_rn(v[0] - __half2float(h0));
    __half l1 = __float2half_rn(v[1] - __half2float(h1));
    __half l2 = __float2half_rn(v[2] - __half2float(h2));
    __half l3 = __float2half_rn(v[3] - __half2float(h3));
    hu.x = pack_h2(h0, h1); hu.y = pack_h2(h2, h3);
    lu.x = pack_h2(l0, l1); lu.y = pack_h2(l2, l3);
}

// ---------------------------------------------------------------------------
// Kernel 1: QKV GEMM via mma.sync, 3-term fp16 split (unchanged, 51us).
// ---------------------------------------------------------------------------
constexpr int QK_SMEM = 36864;

__global__ __launch_bounds__(256) void qkv_mma_kernel(
    const float* __restrict__ x, const float* __restrict__ W,
    const float* __restrict__ bias)
{
    __shared__ __align__(16) char sm[QK_SMEM];
    __half* Ah = (__half*)sm;                    // [32 k][136 m-halves] rows 272B
    __half* Al = (__half*)(sm + 8704);
    __half* Wh = (__half*)(sm + 17408);          // [32 k][72 n-halves] rows 144B
    __half* Wl = (__half*)(sm + 22016);
    float*  Ss = (float*)sm;                     // epilogue: [128 m][72 f32]

    const int tid = threadIdx.x, lane = tid & 31, w = tid >> 5;
    const int jc0 = blockIdx.x * 64;
    const int r0  = blockIdx.y * 128;
    const int b   = r0 >> 12, n0 = r0 & (N_ - 1);
    const float* xb = x + (size_t)b * C_ * N_;

    const uint32_t Ah_s = smem_u32(Ah), Al_s = smem_u32(Al);
    const uint32_t Wh_s = smem_u32(Wh), Wl_s = smem_u32(Wl);

    const int g = lane >> 3, lr = lane & 7;
    const uint32_t a_off = (uint32_t)((g >> 1) * 8 + lr) * 272
                         + (uint32_t)(w * 16 + (g & 1) * 8) * 2;
    const uint32_t b_off = (uint32_t)((g >> 1) * 8 + lr) * 144 + (uint32_t)((g & 1) * 16);

    float acc[8][4];
    #pragma unroll
    for (int i = 0; i < 8; i++)
        #pragma unroll
        for (int j = 0; j < 4; j++) acc[i][j] = 0.f;

    for (int k0 = 0; k0 < C_; k0 += 32) {
        #pragma unroll
        for (int s = 0; s < 4; s++) {
            int idx = tid + 256 * s;
            int kr = idx >> 5, c4 = idx & 31;
            float v[4];
            *(float4*)v = *(const float4*)&xb[(size_t)(k0 + kr) * N_ + n0 + c4 * 4];
            uint2 hu, lu; split4(v, hu, lu);
            *(uint2*)((char*)Ah + kr * 272 + c4 * 8) = hu;
            *(uint2*)((char*)Al + kr * 272 + c4 * 8) = lu;
        }
        #pragma unroll
        for (int s = 0; s < 2; s++) {
            int idx = tid + 256 * s;
            int kr = idx >> 4, c4 = idx & 15;
            float v[4];
            *(float4*)v = *(const float4*)&W[(size_t)(k0 + kr) * QKV3 + jc0 + c4 * 4];
            uint2 hu, lu; split4(v, hu, lu);
            *(uint2*)((char*)Wh + kr * 144 + c4 * 8) = hu;
            *(uint2*)((char*)Wl + kr * 144 + c4 * 8) = lu;
        }
        __syncthreads();

        #pragma unroll
        for (int kt = 0; kt < 2; kt++) {
            uint aH[4], aL[4];
            ldsm4t(aH, Ah_s + kt * (16 * 272) + a_off);
            ldsm4t(aL, Al_s + kt * (16 * 272) + a_off);
            #pragma unroll
            for (int gn = 0; gn < 4; gn++) {
                uint bh[4], bl[4];
                ldsm4t(bh, Wh_s + kt * (16 * 144) + gn * 32 + b_off);
                ldsm4t(bl, Wl_s + kt * (16 * 144) + gn * 32 + b_off);
                mma16816(acc[2*gn],   aH, bh[0], bh[2]);
                mma16816(acc[2*gn],   aH, bl[0], bl[2]);
                mma16816(acc[2*gn],   aL, bh[0], bh[2]);
                mma16816(acc[2*gn+1], aH, bh[1], bh[3]);
                mma16816(acc[2*gn+1], aH, bl[1], bl[3]);
                mma16816(acc[2*gn+1], aL, bh[1], bh[3]);
            }
        }
        __syncthreads();
    }

    #pragma unroll
    for (int nt = 0; nt < 8; nt++) {
        int jj = nt * 8 + (lane & 3) * 2;
        int m0 = w * 16 + (lane >> 2);
        Ss[m0 * 72 + jj]           = acc[nt][0];
        Ss[m0 * 72 + jj + 1]       = acc[nt][1];
        Ss[(m0 + 8) * 72 + jj]     = acc[nt][2];
        Ss[(m0 + 8) * 72 + jj + 1] = acc[nt][3];
    }
    __syncthreads();

    const int m = tid >> 1, seg = (tid & 1) * 32;
    const int jg = jc0 + seg;
    const int sel = jg >> 8;                  // 0=q, 1=k, 2=v
    const int hh = (jg & 255) >> 5;
    const int n = (r0 + m) & (N_ - 1);
    const float mul = (sel == 0) ? (SCALE_ * LOG2E_) : 1.0f;
    const size_t obase = ((size_t)(b * H_ + hh) * N_ + n) * HD_;
    __half* hiA = (sel == 0) ? g_qh : ((sel == 1) ? g_kh : g_vh);
    __half* loA = (sel == 1) ? g_kl : g_vl;

    #pragma unroll
    for (int i = 0; i < 8; i++) {
        float v[4];
        *(float4*)v = *(float4*)&Ss[m * 72 + seg + i * 4];
        float4 bv = *(const float4*)&bias[jg + i * 4];
        v[0] = (v[0] + bv.x) * mul; v[1] = (v[1] + bv.y) * mul;
        v[2] = (v[2] + bv.z) * mul; v[3] = (v[3] + bv.w) * mul;
        if (sel == 0) {
            uint2 hu;
            hu.x = cvt_h2(v[0], v[1]); hu.y = cvt_h2(v[2], v[3]);
            *(uint2*)&hiA[obase + i * 4] = hu;
        } else {
            uint2 hu, lu; split4(v, hu, lu);
            *(uint2*)&hiA[obase + i * 4] = hu;
            *(uint2*)&loA[obase + i * 4] = lu;
        }
    }
}

// ---------------------------------------------------------------------------
// Kernel 2: FMHA via mma.sync m16n8k16, 2-term fp16 splits.
//   S = Qhi.Khi + Qhi.Klo ;  P = ex2.f16x2(S) ;  O += Phi.Vhi + Phi.Vlo
//   l via ones-MMA.
// 256 queries per CTA (8 warps x 2 q-tiles): halves K/V L2 traffic vs 128q.
// K/V: 4-stage cp.async ring, prefetch distance 2 (wait_group 2).
// ---------------------------------------------------------------------------
constexpr int ST = 40;
constexpr int KV_STAGE = 10240;   // Kh(2560) Kl(2560) Vh(2560) Vl(2560)
constexpr int SM_Q_OFF = 4 * KV_STAGE;             // 40960
constexpr int ATT_SMEM = SM_Q_OFF + 256 * ST * 2;  // 61440
constexpr uint H2_ONE = 0x3C003C00u;   // fp16x2 {1, 1}

__global__ __launch_bounds__(256, 2) void attn_mma_kernel()
{
    extern __shared__ __align__(16) char dsm[];
    __half* Qh = (__half*)(dsm + SM_Q_OFF);

    const int tid = threadIdx.x;
    const int lane = tid & 31;
    const int w = tid >> 5;           // 0..7

    const int qblk = blockIdx.x & 15;          // 16 q-tiles of 256
    const int bh = blockIdx.x >> 4;
    const int b = bh >> 3, h = bh & 7;
    const size_t hbase = (size_t)(b * H_ + h) * N_;

    const uint32_t kv_s = smem_u32(dsm);

    // fill role: tid<128 -> K hi+lo chunk; tid>=128 -> V hi+lo chunk
    const int fc = tid & 127;
    const int frow = fc >> 2, fcol = fc & 3;
    const bool doV = (tid >> 7) != 0;
    const uint32_t fdst = (uint32_t)(frow * 80 + fcol * 16);
    const size_t fsrc_d = (size_t)frow * HD_ + fcol * 8;

    auto issue_tile = [&](int t) {
        size_t srow = (hbase + (size_t)t * 32) * HD_ + fsrc_d;
        uint32_t sb = kv_s + (t & 3) * KV_STAGE + fdst;
        if (!doV) {
            cp16(sb + 0,    &g_kh[srow]);
            cp16(sb + 2560, &g_kl[srow]);
        } else {
            cp16(sb + 5120, &g_vh[srow]);
            cp16(sb + 7680, &g_vl[srow]);
        }
    };

    // prologue: tiles 0 and 1 in flight
    issue_tile(0);
    CP_COMMIT();
    issue_tile(1);
    CP_COMMIT();

    // ---- Q tile fill (256 rows x 32 halves): 4 chunks per thread
    #pragma unroll
    for (int s = 0; s < 4; s++) {
        int i = tid + s * 256;
        int row = i >> 2, c = i & 3;
        *(uint4*)&Qh[row * ST + c * 8] =
            *(const uint4*)&g_qh[(hbase + (size_t)qblk * 256 + row) * HD_ + c * 8];
    }
    __syncthreads();

    // ---- Q A-fragments: 2 q-tiles of 16 rows per warp (rows w*32 .. w*32+31)
    const uint32_t qh_s = smem_u32(Qh);
    uint aH[2][2][4];   // [qt][dc]
    #pragma unroll
    for (int qt = 0; qt < 2; qt++) {
        uint32_t aoff = (uint32_t)(w * 32 + qt * 16 + (lane & 15)) * (ST * 2)
                      + (lane >> 4) * 16;
        ldsm4(aH[qt][0], qh_s + aoff);
        ldsm4(aH[qt][1], qh_s + aoff + 32);
    }

    const int g = lane >> 3, lr = lane & 7;
    const uint32_t blk_off = (uint32_t)(((g >> 1) << 3) + lr) * (ST * 2) + ((g & 1) << 4);

    float o[2][4][4];
    #pragma unroll
    for (int q = 0; q < 2; q++)
        #pragma unroll
        for (int i = 0; i < 4; i++)
            #pragma unroll
            for (int j = 0; j < 4; j++) o[q][i][j] = 0.f;
    float ol[2][4] = {};

    constexpr int NT = N_ / 32;   // 128
    for (int ti = 0; ti < NT; ti++) {
        if (ti + 2 < NT) issue_tile(ti + 2);
        CP_COMMIT();
        CP_WAIT2();          // tile ti complete (3rd-most-recent group)
        __syncthreads();

        const uint32_t base = kv_s + (ti & 3) * KV_STAGE;
        const uint32_t kh_s = base, kl_s = base + 2560;
        const uint32_t vh_s = base + 5120, vl_s = base + 7680;

        // ---- S = Qhi.Khi + Qhi.Klo for BOTH q-tiles per K-fragment load
        float s[2][4][4];
        #pragma unroll
        for (int q = 0; q < 2; q++)
            #pragma unroll
            for (int i = 0; i < 4; i++)
                #pragma unroll
                for (int j = 0; j < 4; j++) s[q][i][j] = 0.f;

        #pragma unroll
        for (int dc = 0; dc < 2; dc++) {
            #pragma unroll
            for (int np = 0; np < 2; np++) {
                uint kbh[4], kbl[4];
                uint32_t koff = (uint32_t)(np * 16) * (ST * 2) + blk_off + dc * 32;
                ldsm4(kbh, kh_s + koff);
                ldsm4(kbl, kl_s + koff);
                #pragma unroll
                for (int qt = 0; qt < 2; qt++) {
                    mma16816(s[qt][2*np],   aH[qt][dc], kbh[0], kbh[1]);
                    mma16816(s[qt][2*np],   aH[qt][dc], kbl[0], kbl[1]);
                    mma16816(s[qt][2*np+1], aH[qt][dc], kbh[2], kbh[3]);
                    mma16816(s[qt][2*np+1], aH[qt][dc], kbl[2], kbl[3]);
                }
            }
        }

        // ---- P = exp2(S), packed fp16
        uint pH[2][2][4];
        #pragma unroll
        for (int qt = 0; qt < 2; qt++) {
            #pragma unroll
            for (int nt = 0; nt < 4; nt++) {
                int kc = nt >> 1, pos = (nt & 1) * 2;
                pH[qt][kc][pos]     = ex2h2(cvt_h2(s[qt][nt][0], s[qt][nt][1]));
                pH[qt][kc][pos + 1] = ex2h2(cvt_h2(s[qt][nt][2], s[qt][nt][3]));
            }
        }

        // ---- O += Phi.Vhi + Phi.Vlo ; l += P.1  (V frags shared across q-tiles)
        #pragma unroll
        for (int kc = 0; kc < 2; kc++) {
            mma16816(ol[0], pH[0][kc], H2_ONE, H2_ONE);
            mma16816(ol[1], pH[1][kc], H2_ONE, H2_ONE);
            #pragma unroll
            for (int dp = 0; dp < 2; dp++) {
                uint vbh[4], vbl[4];
                uint32_t voff = (uint32_t)(kc * 16) * (ST * 2) + blk_off + dp * 32;
                ldsm4t(vbh, vh_s + voff);
                ldsm4t(vbl, vl_s + voff);
                #pragma unroll
                for (int qt = 0; qt < 2; qt++) {
                    mma16816(o[qt][2*dp],   pH[qt][kc], vbh[0], vbh[2]);
                    mma16816(o[qt][2*dp],   pH[qt][kc], vbl[0], vbl[2]);
                    mma16816(o[qt][2*dp+1], pH[qt][kc], vbh[1], vbh[3]);
                    mma16816(o[qt][2*dp+1], pH[qt][kc], vbl[1], vbl[3]);
                }
            }
        }
        // reuse safety: write at iter ti targets stage (ti+2)&3, whose prior
        // tile (ti-2) was last read at iter ti-2 — separated by the barriers
        // of iters ti-1 and ti.
    }

    // ---- epilogue: normalize, split hi/lo, write
    const int r = lane >> 2, cpair = (lane & 3) * 2;
    #pragma unroll
    for (int qt = 0; qt < 2; qt++) {
        float inv0 = 1.0f / ol[qt][0], inv1 = 1.0f / ol[qt][2];
        const size_t row0 = (size_t)(b * N_ + qblk * 256 + w * 32 + qt * 16 + r) * C_
                          + h * HD_;
        const size_t row1 = row0 + (size_t)8 * C_;
        #pragma unroll
        for (int nt = 0; nt < 4; nt++) {
            float a0 = o[qt][nt][0] * inv0, a1 = o[qt][nt][1] * inv0;
            float a2 = o[qt][nt][2] * inv1, a3 = o[qt][nt][3] * inv1;
            __half h0 = __float2half_rn(a0), h1 = __float2half_rn(a1);
            __half h2 = __float2half_rn(a2), h3 = __float2half_rn(a3);
            __half l0 = __float2half_rn(a0 - __half2float(h0));
            __half l1 = __float2half_rn(a1 - __half2float(h1));
            __half l2 = __float2half_rn(a2 - __half2float(h2));
            __half l3 = __float2half_rn(a3 - __half2float(h3));
            *(uint*)&g_ah[row0 + nt * 8 + cpair] = pack_h2(h0, h1);
            *(uint*)&g_al[row0 + nt * 8 + cpair] = pack_h2(l0, l1);
            *(uint*)&g_ah[row1 + nt * 8 + cpair] = pack_h2(h2, h3);
            *(uint*)&g_al[row1 + nt * 8 + cpair] = pack_h2(l2, l3);
        }
    }
}

// ---------------------------------------------------------------------------
// Kernel 3: proj GEMM via mma.sync, 3-term split (unchanged, ~33us).
// ---------------------------------------------------------------------------
constexpr int PJ_SMEM = 33792;

__global__ __launch_bounds__(256) void proj_mma_kernel(
    const float* __restrict__ W, const float* __restrict__ bias,
    float* __restrict__ out)
{
    __shared__ __align__(16) char sm[PJ_SMEM];
    __half* Am = (__half*)sm;                    // [128 m][40 k-halves] rows 80B
    __half* Al = (__half*)(sm + 10240);
    __half* Wh = (__half*)(sm + 20480);          // [32 k][72 n-halves] rows 144B
    __half* Wl = (__half*)(sm + 25088);
    float*  Ss = (float*)sm;                     // epilogue: [64 c][132 f32]

    const int tid = threadIdx.x, lane = tid & 31, w = tid >> 5;
    const int jc0 = blockIdx.x * 64;
    const int r0  = blockIdx.y * 128;
    const int b   = r0 >> 12, n0 = r0 & (N_ - 1);

    const uint32_t Am_s = smem_u32(Am), Al_s = smem_u32(Al);
    const uint32_t Wh_s = smem_u32(Wh), Wl_s = smem_u32(Wl);

    const int g = lane >> 3, lr = lane & 7;
    const uint32_t a_off = (uint32_t)(w * 16 + (lane & 15)) * 80 + (uint32_t)(lane >> 4) * 16;
    const uint32_t b_off = (uint32_t)((g >> 1) * 8 + lr) * 144 + (uint32_t)((g & 1) * 16);

    float acc[8][4];
    #pragma unroll
    for (int i = 0; i < 8; i++)
        #pragma unroll
        for (int j = 0; j < 4; j++) acc[i][j] = 0.f;

    for (int k0 = 0; k0 < C_; k0 += 32) {
        #pragma unroll
        for (int s = 0; s < 4; s++) {
            int idx = tid + 256 * s;
            int arr = idx >> 9, rem = idx & 511;
            int row = rem >> 2, c = rem & 3;
            const __half* src = (arr ? g_al : g_ah) + (size_t)(r0 + row) * C_ + k0 + c * 8;
            *(uint4*)((char*)(arr ? Al : Am) + row * 80 + c * 16) = *(const uint4*)src;
        }
        #pragma unroll
        for (int s = 0; s < 2; s++) {
            int idx = tid + 256 * s;
            int kr = idx >> 4, c4 = idx & 15;
            float v[4];
            *(float4*)v = *(const float4*)&W[(size_t)(k0 + kr) * C_ + jc0 + c4 * 4];
            uint2 hu, lu; split4(v, hu, lu);
            *(uint2*)((char*)Wh + kr * 144 + c4 * 8) = hu;
            *(uint2*)((char*)Wl + kr * 144 + c4 * 8) = lu;
        }
        __syncthreads();

        #pragma unroll
        for (int kt = 0; kt < 2; kt++) {
            uint aH[4], aL[4];
            ldsm4(aH, Am_s + a_off + kt * 32);
            ldsm4(aL, Al_s + a_off + kt * 32);
            #pragma unroll
            for (int gn = 0; gn < 4; gn++) {
                uint bh[4], bl[4];
                ldsm4t(bh, Wh_s + kt * (16 * 144) + gn * 32 + b_off);
                ldsm4t(bl, Wl_s + kt * (16 * 144) + gn * 32 + b_off);
                mma16816(acc[2*gn],   aH, bh[0], bh[2]);
                mma16816(acc[2*gn],   aH, bl[0], bl[2]);
                mma16816(acc[2*gn],   aL, bh[0], bh[2]);
                mma16816(acc[2*gn+1], aH, bh[1], bh[3]);
                mma16816(acc[2*gn+1], aH, bl[1], bl[3]);
                mma16816(acc[2*gn+1], aL, bh[1], bh[3]);
            }
        }
        __syncthreads();
    }

    #pragma unroll
    for (int nt = 0; nt < 8; nt++) {
        int cc = nt * 8 + (lane & 3) * 2;
        int m0 = w * 16 + (lane >> 2);
        Ss[cc * 132 + m0]           = acc[nt][0];
        Ss[(cc + 1) * 132 + m0]     = acc[nt][1];
        Ss[cc * 132 + m0 + 8]       = acc[nt][2];
        Ss[(cc + 1) * 132 + m0 + 8] = acc[nt][3];
    }
    __syncthreads();

    const int cc = tid >> 2, nseg = (tid & 3) * 32;
    const float bj = bias[jc0 + cc];
    const size_t ob = ((size_t)b * C_ + jc0 + cc) * N_ + n0 + nseg;
    #pragma unroll
    for (int i = 0; i < 8; i++) {
        float4 v = *(float4*)&Ss[cc * 132 + nseg + i * 4];
        v.x += bj; v.y += bj; v.z += bj; v.w += bj;
        *(float4*)&out[ob + i * 4] = v;
    }
}

// ---------------------------------------------------------------------------
extern "C" void kernel_launch(void* const* d_in, const int* in_sizes, int n_in,
                              void* d_out, int out_size)
{
    const float* x     = (const float*)d_in[0];
    const float* Wqkv  = (const float*)d_in[1];
    const float* bqkv  = (const float*)d_in[2];
    const float* Wproj = (const float*)d_in[3];
    const float* bproj = (const float*)d_in[4];
    float* out = (float*)d_out;

    cudaFuncSetAttribute(attn_mma_kernel,
                         cudaFuncAttributeMaxDynamicSharedMemorySize, ATT_SMEM);

    qkv_mma_kernel<<<dim3(QKV3 / 64, (B_ * N_) / 128), 256>>>(x, Wqkv, bqkv);
    attn_mma_kernel<<<B_ * H_ * (N_ / 256), 256, ATT_SMEM>>>();
    proj_mma_kernel<<<dim3(C_ / 64, (B_ * N_) / 128), 256>>>(Wproj, bproj, out);
}

// round 16
// speedup vs baseline: 1.1895x; 1.1895x over previous
#include <cuda_runtime.h>
#include <cuda_fp16.h>
#include <cstdint>

typedef unsigned int uint;

// Problem constants
constexpr int B_  = 2;
constexpr int C_  = 256;
constexpr int N_  = 4096;
constexpr int H_  = 8;
constexpr int HD_ = 32;
constexpr int QKV3 = 3 * C_;                 // 768
constexpr float SCALE_ = 0.17677669529663689f; // 32^-0.5
constexpr float LOG2E_ = 1.4426950408889634f;

// Scratch (device globals). Q/K hi-only; V/att split fp16 hi/lo.
__device__ __half g_qh[(size_t)B_ * H_ * N_ * HD_];
__device__ __half g_kh[(size_t)B_ * H_ * N_ * HD_];
__device__ __half g_vh[(size_t)B_ * H_ * N_ * HD_];
__device__ __half g_vl[(size_t)B_ * H_ * N_ * HD_];
__device__ __half g_ah[(size_t)B_ * N_ * C_];   // attention out hi, [B*N][C]
__device__ __half g_al[(size_t)B_ * N_ * C_];   // attention out lo

// ---- helpers ----------------------------------------------------------------
__device__ __forceinline__ uint32_t smem_u32(const void* p) {
    uint32_t a;
    asm("{ .reg .u64 t; cvta.to.shared.u64 t, %1; cvt.u32.u64 %0, t; }" : "=r"(a) : "l"(p));
    return a;
}
__device__ __forceinline__ void ldsm4(uint* r, uint32_t addr) {
    asm volatile("ldmatrix.sync.aligned.m8n8.x4.shared.b16 {%0,%1,%2,%3}, [%4];"
        : "=r"(r[0]), "=r"(r[1]), "=r"(r[2]), "=r"(r[3]) : "r"(addr));
}
__device__ __forceinline__ void ldsm4t(uint* r, uint32_t addr) {
    asm volatile("ldmatrix.sync.aligned.m8n8.x4.trans.shared.b16 {%0,%1,%2,%3}, [%4];"
        : "=r"(r[0]), "=r"(r[1]), "=r"(r[2]), "=r"(r[3]) : "r"(addr));
}
__device__ __forceinline__ void mma16816(float* d, const uint* a, uint b0, uint b1) {
    asm volatile(
        "mma.sync.aligned.m16n8k16.row.col.f32.f16.f16.f32 "
        "{%0,%1,%2,%3}, {%4,%5,%6,%7}, {%8,%9}, {%0,%1,%2,%3};"
        : "+f"(d[0]), "+f"(d[1]), "+f"(d[2]), "+f"(d[3])
        : "r"(a[0]), "r"(a[1]), "r"(a[2]), "r"(a[3]), "r"(b0), "r"(b1));
}
__device__ __forceinline__ uint pack_h2(__half a, __half b) {
    unsigned short x = *(unsigned short*)&a, y = *(unsigned short*)&b;
    uint r; asm("mov.b32 %0, {%1, %2};" : "=r"(r) : "h"(x), "h"(y)); return r;
}
__device__ __forceinline__ uint cvt_h2(float a, float b) {
    uint r; asm("cvt.rn.f16x2.f32 %0, %2, %1;" : "=r"(r) : "f"(a), "f"(b)); return r;
}
__device__ __forceinline__ uint ex2h2(uint x) {    // packed fp16x2 exp2
    uint r; asm("ex2.approx.f16x2 %0, %1;" : "=r"(r) : "r"(x)); return r;
}
__device__ __forceinline__ void cp16(uint32_t saddr, const void* gptr) {
    asm volatile("cp.async.cg.shared.global [%0], [%1], 16;" :: "r"(saddr), "l"(gptr));
}
#define CP_COMMIT() asm volatile("cp.async.commit_group;" ::: "memory")
#define CP_WAIT1()  asm volatile("cp.async.wait_group 1;" ::: "memory")

// split 4 floats to hi/lo packed pairs
__device__ __forceinline__ void split4(const float* v, uint2& hu, uint2& lu) {
    __half h0 = __float2half_rn(v[0]), h1 = __float2half_rn(v[1]);
    __half h2 = __float2half_rn(v[2]), h3 = __float2half_rn(v[3]);
    __half l0 = __float2half_rn(v[0] - __half2float(h0));
    __half l1 = __float2half_rn(v[1] - __half2float(h1));
    __half l2 = __float2half_rn(v[2] - __half2float(h2));
    __half l3 = __float2half_rn(v[3] - __half2float(h3));
    hu.x = pack_h2(h0, h1); hu.y = pack_h2(h2, h3);
    lu.x = pack_h2(l0, l1); lu.y = pack_h2(l2, l3);
}

// ---------------------------------------------------------------------------
// Kernel 1: QKV GEMM via mma.sync, 3-term fp16 split. Q/K write hi only.
// ---------------------------------------------------------------------------
constexpr int QK_SMEM = 36864;

__global__ __launch_bounds__(256) void qkv_mma_kernel(
    const float* __restrict__ x, const float* __restrict__ W,
    const float* __restrict__ bias)
{
    __shared__ __align__(16) char sm[QK_SMEM];
    __half* Ah = (__half*)sm;                    // [32 k][136 m-halves] rows 272B
    __half* Al = (__half*)(sm + 8704);
    __half* Wh = (__half*)(sm + 17408);          // [32 k][72 n-halves] rows 144B
    __half* Wl = (__half*)(sm + 22016);
    float*  Ss = (float*)sm;                     // epilogue: [128 m][72 f32]

    const int tid = threadIdx.x, lane = tid & 31, w = tid >> 5;
    const int jc0 = blockIdx.x * 64;
    const int r0  = blockIdx.y * 128;
    const int b   = r0 >> 12, n0 = r0 & (N_ - 1);
    const float* xb = x + (size_t)b * C_ * N_;

    const uint32_t Ah_s = smem_u32(Ah), Al_s = smem_u32(Al);
    const uint32_t Wh_s = smem_u32(Wh), Wl_s = smem_u32(Wl);

    const int g = lane >> 3, lr = lane & 7;
    const uint32_t a_off = (uint32_t)((g >> 1) * 8 + lr) * 272
                         + (uint32_t)(w * 16 + (g & 1) * 8) * 2;
    const uint32_t b_off = (uint32_t)((g >> 1) * 8 + lr) * 144 + (uint32_t)((g & 1) * 16);

    float acc[8][4];
    #pragma unroll
    for (int i = 0; i < 8; i++)
        #pragma unroll
        for (int j = 0; j < 4; j++) acc[i][j] = 0.f;

    for (int k0 = 0; k0 < C_; k0 += 32) {
        #pragma unroll
        for (int s = 0; s < 4; s++) {
            int idx = tid + 256 * s;
            int kr = idx >> 5, c4 = idx & 31;
            float v[4];
            *(float4*)v = *(const float4*)&xb[(size_t)(k0 + kr) * N_ + n0 + c4 * 4];
            uint2 hu, lu; split4(v, hu, lu);
            *(uint2*)((char*)Ah + kr * 272 + c4 * 8) = hu;
            *(uint2*)((char*)Al + kr * 272 + c4 * 8) = lu;
        }
        #pragma unroll
        for (int s = 0; s < 2; s++) {
            int idx = tid + 256 * s;
            int kr = idx >> 4, c4 = idx & 15;
            float v[4];
            *(float4*)v = *(const float4*)&W[(size_t)(k0 + kr) * QKV3 + jc0 + c4 * 4];
            uint2 hu, lu; split4(v, hu, lu);
            *(uint2*)((char*)Wh + kr * 144 + c4 * 8) = hu;
            *(uint2*)((char*)Wl + kr * 144 + c4 * 8) = lu;
        }
        __syncthreads();

        #pragma unroll
        for (int kt = 0; kt < 2; kt++) {
            uint aH[4], aL[4];
            ldsm4t(aH, Ah_s + kt * (16 * 272) + a_off);
            ldsm4t(aL, Al_s + kt * (16 * 272) + a_off);
            #pragma unroll
            for (int gn = 0; gn < 4; gn++) {
                uint bh[4], bl[4];
                ldsm4t(bh, Wh_s + kt * (16 * 144) + gn * 32 + b_off);
                ldsm4t(bl, Wl_s + kt * (16 * 144) + gn * 32 + b_off);
                mma16816(acc[2*gn],   aH, bh[0], bh[2]);
                mma16816(acc[2*gn],   aH, bl[0], bl[2]);
                mma16816(acc[2*gn],   aL, bh[0], bh[2]);
                mma16816(acc[2*gn+1], aH, bh[1], bh[3]);
                mma16816(acc[2*gn+1], aH, bl[1], bl[3]);
                mma16816(acc[2*gn+1], aL, bh[1], bh[3]);
            }
        }
        __syncthreads();
    }

    #pragma unroll
    for (int nt = 0; nt < 8; nt++) {
        int jj = nt * 8 + (lane & 3) * 2;
        int m0 = w * 16 + (lane >> 2);
        Ss[m0 * 72 + jj]           = acc[nt][0];
        Ss[m0 * 72 + jj + 1]       = acc[nt][1];
        Ss[(m0 + 8) * 72 + jj]     = acc[nt][2];
        Ss[(m0 + 8) * 72 + jj + 1] = acc[nt][3];
    }
    __syncthreads();

    const int m = tid >> 1, seg = (tid & 1) * 32;
    const int jg = jc0 + seg;
    const int sel = jg >> 8;                  // 0=q, 1=k, 2=v
    const int hh = (jg & 255) >> 5;
    const int n = (r0 + m) & (N_ - 1);
    const float mul = (sel == 0) ? (SCALE_ * LOG2E_) : 1.0f;
    const size_t obase = ((size_t)(b * H_ + hh) * N_ + n) * HD_;
    __half* hiA = (sel == 0) ? g_qh : ((sel == 1) ? g_kh : g_vh);

    #pragma unroll
    for (int i = 0; i < 8; i++) {
        float v[4];
        *(float4*)v = *(float4*)&Ss[m * 72 + seg + i * 4];
        float4 bv = *(const float4*)&bias[jg + i * 4];
        v[0] = (v[0] + bv.x) * mul; v[1] = (v[1] + bv.y) * mul;
        v[2] = (v[2] + bv.z) * mul; v[3] = (v[3] + bv.w) * mul;
        if (sel < 2) {
            uint2 hu;
            hu.x = cvt_h2(v[0], v[1]); hu.y = cvt_h2(v[2], v[3]);
            *(uint2*)&hiA[obase + i * 4] = hu;
        } else {
            uint2 hu, lu; split4(v, hu, lu);
            *(uint2*)&hiA[obase + i * 4] = hu;
            *(uint2*)&g_vl[obase + i * 4] = lu;
        }
    }
}

// ---------------------------------------------------------------------------
// Kernel 2: FMHA via mma.sync m16n8k16.
//   S = Qhi.Khi (pure fp16 K; exponent error ~2e-4)
//   P = ex2.f16x2(S) ;  O += Phi.Vhi + Phi.Vlo ;  l via ones-MMA
// 4 warps x 32 queries (2 q-tiles/warp, B-frag reuse). 3-stage cp.async ring,
// balanced fill (every thread: Kh+Vh+Vl chunks). 4 CTAs/SM.
// ---------------------------------------------------------------------------
constexpr int ST = 40;
constexpr int KV_STAGE = 7680;    // Kh(2560) Vh(2560) Vl(2560)
constexpr uint H2_ONE = 0x3C003C00u;   // fp16x2 {1, 1}

__global__ __launch_bounds__(128, 4) void attn_mma_kernel()
{
    __shared__ __align__(16) __half Qh[128 * ST];     // 10240 B
    __shared__ __align__(16) char KV[3 * KV_STAGE];   // 23040 B

    const int tid = threadIdx.x;
    const int lane = tid & 31;
    const int w = tid >> 5;           // 0..3

    const int qblk = blockIdx.x & 31;
    const int bh = blockIdx.x >> 5;
    const int b = bh >> 3, h = bh & 7;
    const size_t hbase = (size_t)(b * H_ + h) * N_;

    const uint32_t kv_s = smem_u32(KV);

    // balanced fill: every thread copies one 16B chunk into all THREE arrays
    const int frow = tid >> 2, fcol = tid & 3;      // 32 rows x 4 cols
    const uint32_t fdst = (uint32_t)(frow * 80 + fcol * 16);
    const size_t fsrc_d = (size_t)frow * HD_ + fcol * 8;

    // prologue: issue tile 0 into stage 0
    {
        size_t srow = hbase * HD_ + fsrc_d;
        uint32_t sb = kv_s + fdst;
        cp16(sb + 0,    &g_kh[srow]);
        cp16(sb + 2560, &g_vh[srow]);
        cp16(sb + 5120, &g_vl[srow]);
    }
    CP_COMMIT();

    // ---- Q tile fill (128 rows x 32 halves): 4 chunks per thread
    #pragma unroll
    for (int s = 0; s < 4; s++) {
        int i = tid + s * 128;
        int row = i >> 2, c = i & 3;
        *(uint4*)&Qh[row * ST + c * 8] =
            *(const uint4*)&g_qh[(hbase + (size_t)qblk * 128 + row) * HD_ + c * 8];
    }
    __syncthreads();

    // ---- Q A-fragments: 2 q-tiles of 16 rows per warp
    const uint32_t qh_s = smem_u32(Qh);
    uint aH[2][2][4];   // [qt][dc]
    #pragma unroll
    for (int qt = 0; qt < 2; qt++) {
        uint32_t aoff = (uint32_t)(w * 32 + qt * 16 + (lane & 15)) * (ST * 2)
                      + (lane >> 4) * 16;
        ldsm4(aH[qt][0], qh_s + aoff);
        ldsm4(aH[qt][1], qh_s + aoff + 32);
    }

    const int g = lane >> 3, lr = lane & 7;
    const uint32_t blk_off = (uint32_t)(((g >> 1) << 3) + lr) * (ST * 2) + ((g & 1) << 4);

    float o[2][4][4];
    #pragma unroll
    for (int q = 0; q < 2; q++)
        #pragma unroll
        for (int i = 0; i < 4; i++)
            #pragma unroll
            for (int j = 0; j < 4; j++) o[q][i][j] = 0.f;
    float ol[2][4] = {};

    for (int ti = 0; ti < N_ / 32; ti++) {
        if (ti + 1 < N_ / 32) {
            int stg = (ti + 1) % 3;
            size_t srow = (hbase + (size_t)(ti + 1) * 32) * HD_ + fsrc_d;
            uint32_t sb = kv_s + stg * KV_STAGE + fdst;
            cp16(sb + 0,    &g_kh[srow]);
            cp16(sb + 2560, &g_vh[srow]);
            cp16(sb + 5120, &g_vl[srow]);
        }
        CP_COMMIT();
        CP_WAIT1();
        __syncthreads();

        const uint32_t base = kv_s + (ti % 3) * KV_STAGE;
        const uint32_t kh_s = base;
        const uint32_t vh_s = base + 2560, vl_s = base + 5120;

        // ---- S = Qhi.Khi for BOTH q-tiles per K-fragment load
        float s[2][4][4];
        #pragma unroll
        for (int q = 0; q < 2; q++)
            #pragma unroll
            for (int i = 0; i < 4; i++)
                #pragma unroll
                for (int j = 0; j < 4; j++) s[q][i][j] = 0.f;

        #pragma unroll
        for (int dc = 0; dc < 2; dc++) {
            #pragma unroll
            for (int np = 0; np < 2; np++) {
                uint kbh[4];
                uint32_t koff = (uint32_t)(np * 16) * (ST * 2) + blk_off + dc * 32;
                ldsm4(kbh, kh_s + koff);
                #pragma unroll
                for (int qt = 0; qt < 2; qt++) {
                    mma16816(s[qt][2*np],   aH[qt][dc], kbh[0], kbh[1]);
                    mma16816(s[qt][2*np+1], aH[qt][dc], kbh[2], kbh[3]);
                }
            }
        }

        // ---- P = exp2(S), packed fp16
        uint pH[2][2][4];
        #pragma unroll
        for (int qt = 0; qt < 2; qt++) {
            #pragma unroll
            for (int nt = 0; nt < 4; nt++) {
                int kc = nt >> 1, pos = (nt & 1) * 2;
                pH[qt][kc][pos]     = ex2h2(cvt_h2(s[qt][nt][0], s[qt][nt][1]));
                pH[qt][kc][pos + 1] = ex2h2(cvt_h2(s[qt][nt][2], s[qt][nt][3]));
            }
        }

        // ---- O += Phi.Vhi + Phi.Vlo ; l += P.1  (V frags shared across q-tiles)
        #pragma unroll
        for (int kc = 0; kc < 2; kc++) {
            mma16816(ol[0], pH[0][kc], H2_ONE, H2_ONE);
            mma16816(ol[1], pH[1][kc], H2_ONE, H2_ONE);
            #pragma unroll
            for (int dp = 0; dp < 2; dp++) {
                uint vbh[4], vbl[4];
                uint32_t voff = (uint32_t)(kc * 16) * (ST * 2) + blk_off + dp * 32;
                ldsm4t(vbh, vh_s + voff);
                ldsm4t(vbl, vl_s + voff);
                #pragma unroll
                for (int qt = 0; qt < 2; qt++) {
                    mma16816(o[qt][2*dp],   pH[qt][kc], vbh[0], vbh[2]);
                    mma16816(o[qt][2*dp],   pH[qt][kc], vbl[0], vbl[2]);
                    mma16816(o[qt][2*dp+1], pH[qt][kc], vbh[1], vbh[3]);
                    mma16816(o[qt][2*dp+1], pH[qt][kc], vbl[1], vbl[3]);
                }
            }
        }
    }

    // ---- epilogue: normalize, split hi/lo, write
    const int r = lane >> 2, cpair = (lane & 3) * 2;
    #pragma unroll
    for (int qt = 0; qt < 2; qt++) {
        float inv0 = 1.0f / ol[qt][0], inv1 = 1.0f / ol[qt][2];
        const size_t row0 = (size_t)(b * N_ + qblk * 128 + w * 32 + qt * 16 + r) * C_
                          + h * HD_;
        const size_t row1 = row0 + (size_t)8 * C_;
        #pragma unroll
        for (int nt = 0; nt < 4; nt++) {
            float a0 = o[qt][nt][0] * inv0, a1 = o[qt][nt][1] * inv0;
            float a2 = o[qt][nt][2] * inv1, a3 = o[qt][nt][3] * inv1;
            __half h0 = __float2half_rn(a0), h1 = __float2half_rn(a1);
            __half h2 = __float2half_rn(a2), h3 = __float2half_rn(a3);
            __half l0 = __float2half_rn(a0 - __half2float(h0));
            __half l1 = __float2half_rn(a1 - __half2float(h1));
            __half l2 = __float2half_rn(a2 - __half2float(h2));
            __half l3 = __float2half_rn(a3 - __half2float(h3));
            *(uint*)&g_ah[row0 + nt * 8 + cpair] = pack_h2(h0, h1);
            *(uint*)&g_al[row0 + nt * 8 + cpair] = pack_h2(l0, l1);
            *(uint*)&g_ah[row1 + nt * 8 + cpair] = pack_h2(h2, h3);
            *(uint*)&g_al[row1 + nt * 8 + cpair] = pack_h2(l2, l3);
        }
    }
}

// ---------------------------------------------------------------------------
// Kernel 3: proj GEMM via mma.sync, 3-term split (unchanged, ~33us).
// ---------------------------------------------------------------------------
constexpr int PJ_SMEM = 33792;

__global__ __launch_bounds__(256) void proj_mma_kernel(
    const float* __restrict__ W, const float* __restrict__ bias,
    float* __restrict__ out)
{
    __shared__ __align__(16) char sm[PJ_SMEM];
    __half* Am = (__half*)sm;                    // [128 m][40 k-halves] rows 80B
    __half* Al = (__half*)(sm + 10240);
    __half* Wh = (__half*)(sm + 20480);          // [32 k][72 n-halves] rows 144B
    __half* Wl = (__half*)(sm + 25088);
    float*  Ss = (float*)sm;                     // epilogue: [64 c][132 f32]

    const int tid = threadIdx.x, lane = tid & 31, w = tid >> 5;
    const int jc0 = blockIdx.x * 64;
    const int r0  = blockIdx.y * 128;
    const int b   = r0 >> 12, n0 = r0 & (N_ - 1);

    const uint32_t Am_s = smem_u32(Am), Al_s = smem_u32(Al);
    const uint32_t Wh_s = smem_u32(Wh), Wl_s = smem_u32(Wl);

    const int g = lane >> 3, lr = lane & 7;
    const uint32_t a_off = (uint32_t)(w * 16 + (lane & 15)) * 80 + (uint32_t)(lane >> 4) * 16;
    const uint32_t b_off = (uint32_t)((g >> 1) * 8 + lr) * 144 + (uint32_t)((g & 1) * 16);

    float acc[8][4];
    #pragma unroll
    for (int i = 0; i < 8; i++)
        #pragma unroll
        for (int j = 0; j < 4; j++) acc[i][j] = 0.f;

    for (int k0 = 0; k0 < C_; k0 += 32) {
        #pragma unroll
        for (int s = 0; s < 4; s++) {
            int idx = tid + 256 * s;
            int arr = idx >> 9, rem = idx & 511;
            int row = rem >> 2, c = rem & 3;
            const __half* src = (arr ? g_al : g_ah) + (size_t)(r0 + row) * C_ + k0 + c * 8;
            *(uint4*)((char*)(arr ? Al : Am) + row * 80 + c * 16) = *(const uint4*)src;
        }
        #pragma unroll
        for (int s = 0; s < 2; s++) {
            int idx = tid + 256 * s;
            int kr = idx >> 4, c4 = idx & 15;
            float v[4];
            *(float4*)v = *(const float4*)&W[(size_t)(k0 + kr) * C_ + jc0 + c4 * 4];
            uint2 hu, lu; split4(v, hu, lu);
            *(uint2*)((char*)Wh + kr * 144 + c4 * 8) = hu;
            *(uint2*)((char*)Wl + kr * 144 + c4 * 8) = lu;
        }
        __syncthreads();

        #pragma unroll
        for (int kt = 0; kt < 2; kt++) {
            uint aH[4], aL[4];
            ldsm4(aH, Am_s + a_off + kt * 32);
            ldsm4(aL, Al_s + a_off + kt * 32);
            #pragma unroll
            for (int gn = 0; gn < 4; gn++) {
                uint bh[4], bl[4];
                ldsm4t(bh, Wh_s + kt * (16 * 144) + gn * 32 + b_off);
                ldsm4t(bl, Wl_s + kt * (16 * 144) + gn * 32 + b_off);
                mma16816(acc[2*gn],   aH, bh[0], bh[2]);
                mma16816(acc[2*gn],   aH, bl[0], bl[2]);
                mma16816(acc[2*gn],   aL, bh[0], bh[2]);
                mma16816(acc[2*gn+1], aH, bh[1], bh[3]);
                mma16816(acc[2*gn+1], aH, bl[1], bl[3]);
                mma16816(acc[2*gn+1], aL, bh[1], bh[3]);
            }
        }
        __syncthreads();
    }

    #pragma unroll
    for (int nt = 0; nt < 8; nt++) {
        int cc = nt * 8 + (lane & 3) * 2;
        int m0 = w * 16 + (lane >> 2);
        Ss[cc * 132 + m0]           = acc[nt][0];
        Ss[(cc + 1) * 132 + m0]     = acc[nt][1];
        Ss[cc * 132 + m0 + 8]       = acc[nt][2];
        Ss[(cc + 1) * 132 + m0 + 8] = acc[nt][3];
    }
    __syncthreads();

    const int cc = tid >> 2, nseg = (tid & 3) * 32;
    const float bj = bias[jc0 + cc];
    const size_t ob = ((size_t)b * C_ + jc0 + cc) * N_ + n0 + nseg;
    #pragma unroll
    for (int i = 0; i < 8; i++) {
        float4 v = *(float4*)&Ss[cc * 132 + nseg + i * 4];
        v.x += bj; v.y += bj; v.z += bj; v.w += bj;
        *(float4*)&out[ob + i * 4] = v;
    }
}

// ---------------------------------------------------------------------------
extern "C" void kernel_launch(void* const* d_in, const int* in_sizes, int n_in,
                              void* d_out, int out_size)
{
    const float* x     = (const float*)d_in[0];
    const float* Wqkv  = (const float*)d_in[1];
    const float* bqkv  = (const float*)d_in[2];
    const float* Wproj = (const float*)d_in[3];
    const float* bproj = (const float*)d_in[4];
    float* out = (float*)d_out;

    qkv_mma_kernel<<<dim3(QKV3 / 64, (B_ * N_) / 128), 256>>>(x, Wqkv, bqkv);
    attn_mma_kernel<<<B_ * H_ * (N_ / 128), 128>>>();
    proj_mma_kernel<<<dim3(C_ / 64, (B_ * N_) / 128), 256>>>(Wproj, bproj, out);
}

// round 17
// speedup vs baseline: 1.4896x; 1.2523x over previous
#include <cuda_runtime.h>
#include <cuda_fp16.h>
#include <cstdint>

typedef unsigned int uint;

// Problem constants
constexpr int B_  = 2;
constexpr int C_  = 256;
constexpr int N_  = 4096;
constexpr int H_  = 8;
constexpr int HD_ = 32;
constexpr int QKV3 = 3 * C_;                 // 768
constexpr float SCALE_ = 0.17677669529663689f; // 32^-0.5
constexpr float LOG2E_ = 1.4426950408889634f;

// Scratch (device globals). Q/K/V hi-only fp16; att split hi/lo.
__device__ __half g_qh[(size_t)B_ * H_ * N_ * HD_];
__device__ __half g_kh[(size_t)B_ * H_ * N_ * HD_];
__device__ __half g_vh[(size_t)B_ * H_ * N_ * HD_];
__device__ __half g_ah[(size_t)B_ * N_ * C_];   // attention out hi, [B*N][C]
__device__ __half g_al[(size_t)B_ * N_ * C_];   // attention out lo

// ---- helpers ----------------------------------------------------------------
__device__ __forceinline__ uint32_t smem_u32(const void* p) {
    uint32_t a;
    asm("{ .reg .u64 t; cvta.to.shared.u64 t, %1; cvt.u32.u64 %0, t; }" : "=r"(a) : "l"(p));
    return a;
}
__device__ __forceinline__ void ldsm4(uint* r, uint32_t addr) {
    asm volatile("ldmatrix.sync.aligned.m8n8.x4.shared.b16 {%0,%1,%2,%3}, [%4];"
        : "=r"(r[0]), "=r"(r[1]), "=r"(r[2]), "=r"(r[3]) : "r"(addr));
}
__device__ __forceinline__ void ldsm4t(uint* r, uint32_t addr) {
    asm volatile("ldmatrix.sync.aligned.m8n8.x4.trans.shared.b16 {%0,%1,%2,%3}, [%4];"
        : "=r"(r[0]), "=r"(r[1]), "=r"(r[2]), "=r"(r[3]) : "r"(addr));
}
__device__ __forceinline__ void mma16816(float* d, const uint* a, uint b0, uint b1) {
    asm volatile(
        "mma.sync.aligned.m16n8k16.row.col.f32.f16.f16.f32 "
        "{%0,%1,%2,%3}, {%4,%5,%6,%7}, {%8,%9}, {%0,%1,%2,%3};"
        : "+f"(d[0]), "+f"(d[1]), "+f"(d[2]), "+f"(d[3])
        : "r"(a[0]), "r"(a[1]), "r"(a[2]), "r"(a[3]), "r"(b0), "r"(b1));
}
__device__ __forceinline__ uint pack_h2(__half a, __half b) {
    unsigned short x = *(unsigned short*)&a, y = *(unsigned short*)&b;
    uint r; asm("mov.b32 %0, {%1, %2};" : "=r"(r) : "h"(x), "h"(y)); return r;
}
__device__ __forceinline__ uint cvt_h2(float a, float b) {
    uint r; asm("cvt.rn.f16x2.f32 %0, %2, %1;" : "=r"(r) : "f"(a), "f"(b)); return r;
}
__device__ __forceinline__ uint ex2h2(uint x) {    // packed fp16x2 exp2
    uint r; asm("ex2.approx.f16x2 %0, %1;" : "=r"(r) : "r"(x)); return r;
}
__device__ __forceinline__ void cp16(uint32_t saddr, const void* gptr) {
    asm volatile("cp.async.cg.shared.global [%0], [%1], 16;" :: "r"(saddr), "l"(gptr));
}
#define CP_COMMIT() asm volatile("cp.async.commit_group;" ::: "memory")
#define CP_WAIT1()  asm volatile("cp.async.wait_group 1;" ::: "memory")

// split 4 floats to hi/lo packed pairs
__device__ __forceinline__ void split4(const float* v, uint2& hu, uint2& lu) {
    __half h0 = __float2half_rn(v[0]), h1 = __float2half_rn(v[1]);
    __half h2 = __float2half_rn(v[2]), h3 = __float2half_rn(v[3]);
    __half l0 = __float2half_rn(v[0] - __half2float(h0));
    __half l1 = __float2half_rn(v[1] - __half2float(h1));
    __half l2 = __float2half_rn(v[2] - __half2float(h2));
    __half l3 = __float2half_rn(v[3] - __half2float(h3));
    hu.x = pack_h2(h0, h1); hu.y = pack_h2(h2, h3);
    lu.x = pack_h2(l0, l1); lu.y = pack_h2(l2, l3);
}

// ---------------------------------------------------------------------------
// Kernel 1: QKV GEMM via mma.sync, 3-term fp16 split. Q/K/V all write hi only.
// ---------------------------------------------------------------------------
constexpr int QK_SMEM = 36864;

__global__ __launch_bounds__(256) void qkv_mma_kernel(
    const float* __restrict__ x, const float* __restrict__ W,
    const float* __restrict__ bias)
{
    __shared__ __align__(16) char sm[QK_SMEM];
    __half* Ah = (__half*)sm;                    // [32 k][136 m-halves] rows 272B
    __half* Al = (__half*)(sm + 8704);
    __half* Wh = (__half*)(sm + 17408);          // [32 k][72 n-halves] rows 144B
    __half* Wl = (__half*)(sm + 22016);
    float*  Ss = (float*)sm;                     // epilogue: [128 m][72 f32]

    const int tid = threadIdx.x, lane = tid & 31, w = tid >> 5;
    const int jc0 = blockIdx.x * 64;
    const int r0  = blockIdx.y * 128;
    const int b   = r0 >> 12, n0 = r0 & (N_ - 1);
    const float* xb = x + (size_t)b * C_ * N_;

    const uint32_t Ah_s = smem_u32(Ah), Al_s = smem_u32(Al);
    const uint32_t Wh_s = smem_u32(Wh), Wl_s = smem_u32(Wl);

    const int g = lane >> 3, lr = lane & 7;
    const uint32_t a_off = (uint32_t)((g >> 1) * 8 + lr) * 272
                         + (uint32_t)(w * 16 + (g & 1) * 8) * 2;
    const uint32_t b_off = (uint32_t)((g >> 1) * 8 + lr) * 144 + (uint32_t)((g & 1) * 16);

    float acc[8][4];
    #pragma unroll
    for (int i = 0; i < 8; i++)
        #pragma unroll
        for (int j = 0; j < 4; j++) acc[i][j] = 0.f;

    for (int k0 = 0; k0 < C_; k0 += 32) {
        #pragma unroll
        for (int s = 0; s < 4; s++) {
            int idx = tid + 256 * s;
            int kr = idx >> 5, c4 = idx & 31;
            float v[4];
            *(float4*)v = *(const float4*)&xb[(size_t)(k0 + kr) * N_ + n0 + c4 * 4];
            uint2 hu, lu; split4(v, hu, lu);
            *(uint2*)((char*)Ah + kr * 272 + c4 * 8) = hu;
            *(uint2*)((char*)Al + kr * 272 + c4 * 8) = lu;
        }
        #pragma unroll
        for (int s = 0; s < 2; s++) {
            int idx = tid + 256 * s;
            int kr = idx >> 4, c4 = idx & 15;
            float v[4];
            *(float4*)v = *(const float4*)&W[(size_t)(k0 + kr) * QKV3 + jc0 + c4 * 4];
            uint2 hu, lu; split4(v, hu, lu);
            *(uint2*)((char*)Wh + kr * 144 + c4 * 8) = hu;
            *(uint2*)((char*)Wl + kr * 144 + c4 * 8) = lu;
        }
        __syncthreads();

        #pragma unroll
        for (int kt = 0; kt < 2; kt++) {
            uint aH[4], aL[4];
            ldsm4t(aH, Ah_s + kt * (16 * 272) + a_off);
            ldsm4t(aL, Al_s + kt * (16 * 272) + a_off);
            #pragma unroll
            for (int gn = 0; gn < 4; gn++) {
                uint bh[4], bl[4];
                ldsm4t(bh, Wh_s + kt * (16 * 144) + gn * 32 + b_off);
                ldsm4t(bl, Wl_s + kt * (16 * 144) + gn * 32 + b_off);
                mma16816(acc[2*gn],   aH, bh[0], bh[2]);
                mma16816(acc[2*gn],   aH, bl[0], bl[2]);
                mma16816(acc[2*gn],   aL, bh[0], bh[2]);
                mma16816(acc[2*gn+1], aH, bh[1], bh[3]);
                mma16816(acc[2*gn+1], aH, bl[1], bl[3]);
                mma16816(acc[2*gn+1], aL, bh[1], bh[3]);
            }
        }
        __syncthreads();
    }

    #pragma unroll
    for (int nt = 0; nt < 8; nt++) {
        int jj = nt * 8 + (lane & 3) * 2;
        int m0 = w * 16 + (lane >> 2);
        Ss[m0 * 72 + jj]           = acc[nt][0];
        Ss[m0 * 72 + jj + 1]       = acc[nt][1];
        Ss[(m0 + 8) * 72 + jj]     = acc[nt][2];
        Ss[(m0 + 8) * 72 + jj + 1] = acc[nt][3];
    }
    __syncthreads();

    const int m = tid >> 1, seg = (tid & 1) * 32;
    const int jg = jc0 + seg;
    const int sel = jg >> 8;                  // 0=q, 1=k, 2=v
    const int hh = (jg & 255) >> 5;
    const int n = (r0 + m) & (N_ - 1);
    const float mul = (sel == 0) ? (SCALE_ * LOG2E_) : 1.0f;
    const size_t obase = ((size_t)(b * H_ + hh) * N_ + n) * HD_;
    __half* hiA = (sel == 0) ? g_qh : ((sel == 1) ? g_kh : g_vh);

    #pragma unroll
    for (int i = 0; i < 8; i++) {
        float v[4];
        *(float4*)v = *(float4*)&Ss[m * 72 + seg + i * 4];
        float4 bv = *(const float4*)&bias[jg + i * 4];
        v[0] = (v[0] + bv.x) * mul; v[1] = (v[1] + bv.y) * mul;
        v[2] = (v[2] + bv.z) * mul; v[3] = (v[3] + bv.w) * mul;
        uint2 hu;
        hu.x = cvt_h2(v[0], v[1]); hu.y = cvt_h2(v[2], v[3]);
        *(uint2*)&hiA[obase + i * 4] = hu;
    }
}

// ---------------------------------------------------------------------------
// Kernel 2: FMHA via mma.sync m16n8k16, pure fp16 operands:
//   S = Qhi.Khi ;  P = ex2.f16x2(S) ;  O += Phi.Vhi ;  l via ones-MMA
// (K/V hi-truncation errors: exponent-additive ~2e-4 / output-quadrature ~2.4e-4)
// 4 warps x 32 queries (2 q-tiles/warp, B-frag reuse). 3-stage cp.async ring.
// ---------------------------------------------------------------------------
constexpr int ST = 40;
constexpr int KV_STAGE = 5120;    // Kh(2560) Vh(2560)
constexpr uint H2_ONE = 0x3C003C00u;   // fp16x2 {1, 1}

__global__ __launch_bounds__(128, 4) void attn_mma_kernel()
{
    __shared__ __align__(16) __half Qh[128 * ST];     // 10240 B
    __shared__ __align__(16) char KV[3 * KV_STAGE];   // 15360 B

    const int tid = threadIdx.x;
    const int lane = tid & 31;
    const int w = tid >> 5;           // 0..3

    const int qblk = blockIdx.x & 31;
    const int bh = blockIdx.x >> 5;
    const int b = bh >> 3, h = bh & 7;
    const size_t hbase = (size_t)(b * H_ + h) * N_;

    const uint32_t kv_s = smem_u32(KV);

    // balanced fill: every thread copies one 16B chunk into both arrays
    const int frow = tid >> 2, fcol = tid & 3;      // 32 rows x 4 cols
    const uint32_t fdst = (uint32_t)(frow * 80 + fcol * 16);
    const size_t fsrc_d = (size_t)frow * HD_ + fcol * 8;

    // prologue: issue tile 0 into stage 0
    {
        size_t srow = hbase * HD_ + fsrc_d;
        uint32_t sb = kv_s + fdst;
        cp16(sb + 0,    &g_kh[srow]);
        cp16(sb + 2560, &g_vh[srow]);
    }
    CP_COMMIT();

    // ---- Q tile fill (128 rows x 32 halves): 4 chunks per thread
    #pragma unroll
    for (int s = 0; s < 4; s++) {
        int i = tid + s * 128;
        int row = i >> 2, c = i & 3;
        *(uint4*)&Qh[row * ST + c * 8] =
            *(const uint4*)&g_qh[(hbase + (size_t)qblk * 128 + row) * HD_ + c * 8];
    }
    __syncthreads();

    // ---- Q A-fragments: 2 q-tiles of 16 rows per warp
    const uint32_t qh_s = smem_u32(Qh);
    uint aH[2][2][4];   // [qt][dc]
    #pragma unroll
    for (int qt = 0; qt < 2; qt++) {
        uint32_t aoff = (uint32_t)(w * 32 + qt * 16 + (lane & 15)) * (ST * 2)
                      + (lane >> 4) * 16;
        ldsm4(aH[qt][0], qh_s + aoff);
        ldsm4(aH[qt][1], qh_s + aoff + 32);
    }

    const int g = lane >> 3, lr = lane & 7;
    const uint32_t blk_off = (uint32_t)(((g >> 1) << 3) + lr) * (ST * 2) + ((g & 1) << 4);

    float o[2][4][4];
    #pragma unroll
    for (int q = 0; q < 2; q++)
        #pragma unroll
        for (int i = 0; i < 4; i++)
            #pragma unroll
            for (int j = 0; j < 4; j++) o[q][i][j] = 0.f;
    float ol[2][4] = {};

    for (int ti = 0; ti < N_ / 32; ti++) {
        if (ti + 1 < N_ / 32) {
            int stg = (ti + 1) % 3;
            size_t srow = (hbase + (size_t)(ti + 1) * 32) * HD_ + fsrc_d;
            uint32_t sb = kv_s + stg * KV_STAGE + fdst;
            cp16(sb + 0,    &g_kh[srow]);
            cp16(sb + 2560, &g_vh[srow]);
        }
        CP_COMMIT();
        CP_WAIT1();
        __syncthreads();

        const uint32_t base = kv_s + (ti % 3) * KV_STAGE;
        const uint32_t kh_s = base;
        const uint32_t vh_s = base + 2560;

        // ---- S = Qhi.Khi for BOTH q-tiles per K-fragment load
        float s[2][4][4];
        #pragma unroll
        for (int q = 0; q < 2; q++)
            #pragma unroll
            for (int i = 0; i < 4; i++)
                #pragma unroll
                for (int j = 0; j < 4; j++) s[q][i][j] = 0.f;

        #pragma unroll
        for (int dc = 0; dc < 2; dc++) {
            #pragma unroll
            for (int np = 0; np < 2; np++) {
                uint kbh[4];
                uint32_t koff = (uint32_t)(np * 16) * (ST * 2) + blk_off + dc * 32;
                ldsm4(kbh, kh_s + koff);
                #pragma unroll
                for (int qt = 0; qt < 2; qt++) {
                    mma16816(s[qt][2*np],   aH[qt][dc], kbh[0], kbh[1]);
                    mma16816(s[qt][2*np+1], aH[qt][dc], kbh[2], kbh[3]);
                }
            }
        }

        // ---- P = exp2(S), packed fp16
        uint pH[2][2][4];
        #pragma unroll
        for (int qt = 0; qt < 2; qt++) {
            #pragma unroll
            for (int nt = 0; nt < 4; nt++) {
                int kc = nt >> 1, pos = (nt & 1) * 2;
                pH[qt][kc][pos]     = ex2h2(cvt_h2(s[qt][nt][0], s[qt][nt][1]));
                pH[qt][kc][pos + 1] = ex2h2(cvt_h2(s[qt][nt][2], s[qt][nt][3]));
            }
        }

        // ---- O += Phi.Vhi ; l += P.1  (V frags shared across q-tiles)
        #pragma unroll
        for (int kc = 0; kc < 2; kc++) {
            mma16816(ol[0], pH[0][kc], H2_ONE, H2_ONE);
            mma16816(ol[1], pH[1][kc], H2_ONE, H2_ONE);
            #pragma unroll
            for (int dp = 0; dp < 2; dp++) {
                uint vbh[4];
                uint32_t voff = (uint32_t)(kc * 16) * (ST * 2) + blk_off + dp * 32;
                ldsm4t(vbh, vh_s + voff);
                #pragma unroll
                for (int qt = 0; qt < 2; qt++) {
                    mma16816(o[qt][2*dp],   pH[qt][kc], vbh[0], vbh[2]);
                    mma16816(o[qt][2*dp+1], pH[qt][kc], vbh[1], vbh[3]);
                }
            }
        }
    }

    // ---- epilogue: normalize, split hi/lo, write
    const int r = lane >> 2, cpair = (lane & 3) * 2;
    #pragma unroll
    for (int qt = 0; qt < 2; qt++) {
        float inv0 = 1.0f / ol[qt][0], inv1 = 1.0f / ol[qt][2];
        const size_t row0 = (size_t)(b * N_ + qblk * 128 + w * 32 + qt * 16 + r) * C_
                          + h * HD_;
        const size_t row1 = row0 + (size_t)8 * C_;
        #pragma unroll
        for (int nt = 0; nt < 4; nt++) {
            float a0 = o[qt][nt][0] * inv0, a1 = o[qt][nt][1] * inv0;
            float a2 = o[qt][nt][2] * inv1, a3 = o[qt][nt][3] * inv1;
            __half h0 = __float2half_rn(a0), h1 = __float2half_rn(a1);
            __half h2 = __float2half_rn(a2), h3 = __float2half_rn(a3);
            __half l0 = __float2half_rn(a0 - __half2float(h0));
            __half l1 = __float2half_rn(a1 - __half2float(h1));
            __half l2 = __float2half_rn(a2 - __half2float(h2));
            __half l3 = __float2half_rn(a3 - __half2float(h3));
            *(uint*)&g_ah[row0 + nt * 8 + cpair] = pack_h2(h0, h1);
            *(uint*)&g_al[row0 + nt * 8 + cpair] = pack_h2(l0, l1);
            *(uint*)&g_ah[row1 + nt * 8 + cpair] = pack_h2(h2, h3);
            *(uint*)&g_al[row1 + nt * 8 + cpair] = pack_h2(l2, l3);
        }
    }
}

// ---------------------------------------------------------------------------
// Kernel 3: proj GEMM via mma.sync, 3-term split (unchanged, ~33us).
// ---------------------------------------------------------------------------
constexpr int PJ_SMEM = 33792;

__global__ __launch_bounds__(256) void proj_mma_kernel(
    const float* __restrict__ W, const float* __restrict__ bias,
    float* __restrict__ out)
{
    __shared__ __align__(16) char sm[PJ_SMEM];
    __half* Am = (__half*)sm;                    // [128 m][40 k-halves] rows 80B
    __half* Al = (__half*)(sm + 10240);
    __half* Wh = (__half*)(sm + 20480);          // [32 k][72 n-halves] rows 144B
    __half* Wl = (__half*)(sm + 25088);
    float*  Ss = (float*)sm;                     // epilogue: [64 c][132 f32]

    const int tid = threadIdx.x, lane = tid & 31, w = tid >> 5;
    const int jc0 = blockIdx.x * 64;
    const int r0  = blockIdx.y * 128;
    const int b   = r0 >> 12, n0 = r0 & (N_ - 1);

    const uint32_t Am_s = smem_u32(Am), Al_s = smem_u32(Al);
    const uint32_t Wh_s = smem_u32(Wh), Wl_s = smem_u32(Wl);

    const int g = lane >> 3, lr = lane & 7;
    const uint32_t a_off = (uint32_t)(w * 16 + (lane & 15)) * 80 + (uint32_t)(lane >> 4) * 16;
    const uint32_t b_off = (uint32_t)((g >> 1) * 8 + lr) * 144 + (uint32_t)((g & 1) * 16);

    float acc[8][4];
    #pragma unroll
    for (int i = 0; i < 8; i++)
        #pragma unroll
        for (int j = 0; j < 4; j++) acc[i][j] = 0.f;

    for (int k0 = 0; k0 < C_; k0 += 32) {
        #pragma unroll
        for (int s = 0; s < 4; s++) {
            int idx = tid + 256 * s;
            int arr = idx >> 9, rem = idx & 511;
            int row = rem >> 2, c = rem & 3;
            const __half* src = (arr ? g_al : g_ah) + (size_t)(r0 + row) * C_ + k0 + c * 8;
            *(uint4*)((char*)(arr ? Al : Am) + row * 80 + c * 16) = *(const uint4*)src;
        }
        #pragma unroll
        for (int s = 0; s < 2; s++) {
            int idx = tid + 256 * s;
            int kr = idx >> 4, c4 = idx & 15;
            float v[4];
            *(float4*)v = *(const float4*)&W[(size_t)(k0 + kr) * C_ + jc0 + c4 * 4];
            uint2 hu, lu; split4(v, hu, lu);
            *(uint2*)((char*)Wh + kr * 144 + c4 * 8) = hu;
            *(uint2*)((char*)Wl + kr * 144 + c4 * 8) = lu;
        }
        __syncthreads();

        #pragma unroll
        for (int kt = 0; kt < 2; kt++) {
            uint aH[4], aL[4];
            ldsm4(aH, Am_s + a_off + kt * 32);
            ldsm4(aL, Al_s + a_off + kt * 32);
            #pragma unroll
            for (int gn = 0; gn < 4; gn++) {
                uint bh[4], bl[4];
                ldsm4t(bh, Wh_s + kt * (16 * 144) + gn * 32 + b_off);
                ldsm4t(bl, Wl_s + kt * (16 * 144) + gn * 32 + b_off);
                mma16816(acc[2*gn],   aH, bh[0], bh[2]);
                mma16816(acc[2*gn],   aH, bl[0], bl[2]);
                mma16816(acc[2*gn],   aL, bh[0], bh[2]);
                mma16816(acc[2*gn+1], aH, bh[1], bh[3]);
                mma16816(acc[2*gn+1], aH, bl[1], bl[3]);
                mma16816(acc[2*gn+1], aL, bh[1], bh[3]);
            }
        }
        __syncthreads();
    }

    #pragma unroll
    for (int nt = 0; nt < 8; nt++) {
        int cc = nt * 8 + (lane & 3) * 2;
        int m0 = w * 16 + (lane >> 2);
        Ss[cc * 132 + m0]           = acc[nt][0];
        Ss[(cc + 1) * 132 + m0]     = acc[nt][1];
        Ss[cc * 132 + m0 + 8]       = acc[nt][2];
        Ss[(cc + 1) * 132 + m0 + 8] = acc[nt][3];
    }
    __syncthreads();

    const int cc = tid >> 2, nseg = (tid & 3) * 32;
    const float bj = bias[jc0 + cc];
    const size_t ob = ((size_t)b * C_ + jc0 + cc) * N_ + n0 + nseg;
    #pragma unroll
    for (int i = 0; i < 8; i++) {
        float4 v = *(float4*)&Ss[cc * 132 + nseg + i * 4];
        v.x += bj; v.y += bj; v.z += bj; v.w += bj;
        *(float4*)&out[ob + i * 4] = v;
    }
}

// ---------------------------------------------------------------------------
extern "C" void kernel_launch(void* const* d_in, const int* in_sizes, int n_in,
                              void* d_out, int out_size)
{
    const float* x     = (const float*)d_in[0];
    const float* Wqkv  = (const float*)d_in[1];
    const float* bqkv  = (const float*)d_in[2];
    const float* Wproj = (const float*)d_in[3];
    const float* bproj = (const float*)d_in[4];
    float* out = (float*)d_out;

    qkv_mma_kernel<<<dim3(QKV3 / 64, (B_ * N_) / 128), 256>>>(x, Wqkv, bqkv);
    attn_mma_kernel<<<B_ * H_ * (N_ / 128), 128>>>();
    proj_mma_kernel<<<dim3(C_ / 64, (B_ * N_) / 128), 256>>>(Wproj, bproj, out);
}